// round 6
// baseline (speedup 1.0000x reference)
#include <cuda_runtime.h>
#include <cstdint>

// out4[((b*H+y)*W+x)*768 + ch*4 + i] = float4{ in[b,ch,y+i-3, x-2..x+1] },
// zero-padded; lanes z,w zeroed when i==3. B=8, C=192, H=W=48.
// Block = (b, y, 4-wide x-tile). Smem: [768 chi-rows][pitch 9] = 27648 B.

#define B_   8
#define C_   192
#define H_   48
#define W_   48
#define TX   4
#define XT   (W_ / TX)             // 12
#define PITCH 9                    // cols x0-2 .. x0+6 (gcd(9,32)=1 -> no conflicts)
#define SELEMS (C_ * 4 * PITCH)    // 6912 floats = 27648 B
#define LOAD_ITERS (SELEMS / 256)  // 27

__device__ __forceinline__ void cp_async4(uint32_t saddr, const float* gaddr, bool valid)
{
    const int sz = valid ? 4 : 0;   // src_size=0 -> zero-fill, no global read
    asm volatile("cp.async.ca.shared.global [%0], [%1], 4, %2;\n"
                 :: "r"(saddr), "l"(gaddr), "r"(sz));
}

__global__ void __launch_bounds__(256, 8)
block_sample_smem(const float* __restrict__ in, float4* __restrict__ out)
{
    __shared__ float s[SELEMS];

    const int tid = threadIdx.x;
    int bid = blockIdx.x;
    const int xt = bid % XT;  bid /= XT;
    const int y  = bid % H_;
    const int b  = bid / H_;
    const int x0 = xt * TX;

    const uint32_t sbase = (uint32_t)__cvta_generic_to_shared(s);

    // ---- async load: rows y-3..y, cols x0-2..x0+6, all 192 channels ----
    #pragma unroll
    for (int k = 0; k < LOAD_ITERS; k++) {
        const int idx = k * 256 + tid;
        const int sc  = idx % PITCH;       // 0..8
        const int rf  = idx / PITCH;       // ch*4 + r
        const int gy  = y + (rf & 3) - 3;  // <= 47 always
        const int gx  = x0 - 2 + sc;       // -2 .. 50
        const bool ok = (gy >= 0) & (gx >= 0) & (gx < W_);
        const float* g = in + ((b * C_ + (rf >> 2)) * H_ + gy) * W_ + gx;
        cp_async4(sbase + idx * 4u, g, ok);
    }
    asm volatile("cp.async.commit_group;\n" ::: "memory");
    asm volatile("cp.async.wait_group 0;\n" ::: "memory");
    __syncthreads();

    // ---- store: per chi read 7-word window (conflict-free scalar LDS),
    //      emit 4 sliding, perfectly-coalesced STG.128 ----
    float4* const obase = out + (long)((b * H_ + y) * W_ + x0) * (C_ * 4);
    #pragma unroll
    for (int sub = 0; sub < 3; sub++) {                 // 768 = 3*256
        const int chi = sub * 256 + tid;                // ch*4 + i
        const bool m  = (chi & 3) == 3;                 // i == 3 -> mask z,w
        const float* row = &s[chi * PITCH];
        const float r0 = row[0], r1 = row[1], r2 = row[2], r3 = row[3];
        const float r4 = row[4], r5 = row[5], r6 = row[6];
        const float m2 = m ? 0.f : r2;
        const float m3 = m ? 0.f : r3;
        const float m4 = m ? 0.f : r4;
        const float m5 = m ? 0.f : r5;
        const float m6 = m ? 0.f : r6;
        float4* o = obase + chi;
        __stcs(o,              make_float4(r0, r1, m2, m3));
        __stcs(o + C_ * 4,     make_float4(r1, r2, m3, m4));
        __stcs(o + 2 * C_ * 4, make_float4(r2, r3, m4, m5));
        __stcs(o + 3 * C_ * 4, make_float4(r3, r4, m5, m6));
    }
}

extern "C" void kernel_launch(void* const* d_in, const int* in_sizes, int n_in,
                              void* d_out, int out_size)
{
    const float* in  = (const float*)d_in[0];
    float4*      out = (float4*)d_out;

    const int blocks = B_ * H_ * XT;   // 4608
    block_sample_smem<<<blocks, 256>>>(in, out);
}

// round 7
// speedup vs baseline: 1.3281x; 1.3281x over previous
#include <cuda_runtime.h>

// out4[((b*H+y)*W+x)*768 + ch*4 + i] = float4{ in[b,ch,y+i-3, x-2..x+1] },
// zero-padded; lanes z,w zeroed when i==3. B=8, C=192, H=W=48.
// Block = (b, y, 12-wide x-tile). Smem: [768 chi-rows][pitch 15] = 46080 B.

#define B_   8
#define C_   192
#define H_   48
#define W_   48
#define TX   12
#define XT   (W_ / TX)             // 4 x-tiles per row
#define PITCH 15                   // cols x0-2 .. x0+12 ; gcd(15,32)=1
#define SELEMS (C_ * 4 * PITCH)    // 11520 floats = 46080 B (4 CTAs/SM)
#define LOAD_ITERS (SELEMS / 256)  // 45

__global__ void __launch_bounds__(256)
block_sample_smem(const float* __restrict__ in, float4* __restrict__ out)
{
    __shared__ float s[SELEMS];

    const int tid = threadIdx.x;
    int bid = blockIdx.x;
    const int xt = bid % XT;  bid /= XT;
    const int y  = bid % H_;
    const int b  = bid / H_;
    const int x0 = xt * TX;

    // ---- load: rows y-3..y, cols x0-2..x0+12, all 192 channels ----
    #pragma unroll 9
    for (int k = 0; k < LOAD_ITERS; k++) {
        const int idx = k * 256 + tid;
        const int sc  = idx % PITCH;       // 0..14
        const int rf  = idx / PITCH;       // ch*4 + r
        const int gy  = y + (rf & 3) - 3;  // <= 47 always
        const int gx  = x0 - 2 + sc;       // -2 .. 48
        float v = 0.f;
        if (gy >= 0 && gx >= 0 && gx < W_)
            v = __ldg(in + ((b * C_ + (rf >> 2)) * H_ + gy) * W_ + gx);
        s[idx] = v;
    }
    __syncthreads();

    // ---- store: per chi read 15-word window (conflict-free scalar LDS),
    //      emit 12 independent, perfectly-coalesced streaming STG.128 ----
    float4* const obase = out + (long)((b * H_ + y) * W_ + x0) * (C_ * 4);
    #pragma unroll
    for (int sub = 0; sub < 3; sub++) {                 // 768 = 3*256
        const int chi = sub * 256 + tid;                // ch*4 + i
        const bool msk = (chi & 3) == 3;                // i == 3 -> mask z,w
        const float* row = &s[chi * PITCH];

        float w[PITCH], wm[PITCH];
        #pragma unroll
        for (int c = 0; c < PITCH; c++) w[c] = row[c];
        #pragma unroll
        for (int c = 0; c < PITCH; c++) wm[c] = msk ? 0.f : w[c];

        float4* o = obase + chi;
        #pragma unroll
        for (int xl = 0; xl < TX; xl++) {
            __stcs(o + xl * (C_ * 4),
                   make_float4(w[xl], w[xl + 1], wm[xl + 2], wm[xl + 3]));
        }
    }
}

extern "C" void kernel_launch(void* const* d_in, const int* in_sizes, int n_in,
                              void* d_out, int out_size)
{
    const float* in  = (const float*)d_in[0];
    float4*      out = (float4*)d_out;

    const int blocks = B_ * H_ * XT;   // 1536
    block_sample_smem<<<blocks, 256>>>(in, out);
}